// round 9
// baseline (speedup 1.0000x reference)
#include <cuda_runtime.h>
#include <cuda_bf16.h>
#include <math.h>

// ---------------- Problem constants ----------------
#define V_SZ 50257
#define E_SZ 768
#define H_SZ 12
#define L_SZ 6
#define T_SZ 1024
#define B_SZ 2
#define D_SZ 64
#define BT   (B_SZ * T_SZ)      // 2048
#define FF   (4 * E_SZ)         // 3072
#define QKV_LD (3 * E_SZ)       // 2304

// ---------------- Scratch (device globals; no allocations allowed) ----------
__device__ float g_x   [BT * E_SZ];
__device__ float g_h   [BT * E_SZ];
__device__ float g_qkv [BT * QKV_LD];
__device__ float g_att [BT * E_SZ];
__device__ float g_m1  [BT * FF];
// tf32-rounded weight copies
__device__ float g_wqkv[L_SZ * E_SZ * QKV_LD];
__device__ float g_wo  [L_SZ * E_SZ * E_SZ];
__device__ float g_w1  [L_SZ * E_SZ * FF];
__device__ float g_w2  [L_SZ * E_SZ * FF];
__device__ float g_wte [V_SZ * E_SZ];

// ---------------- tf32 helpers ----------------
__device__ __forceinline__ unsigned f2tf(float f) {
    unsigned u;
    asm("cvt.rna.tf32.f32 %0, %1;" : "=r"(u) : "f"(f));
    return u;
}
__device__ __forceinline__ float rtf(float f) { return __uint_as_float(f2tf(f)); }
__device__ __forceinline__ float4 rtf4(float4 v) {
    v.x = rtf(v.x); v.y = rtf(v.y); v.z = rtf(v.z); v.w = rtf(v.w);
    return v;
}

// round-convert fp32 array to tf32-representable fp32
__global__ void cvt_kernel(const float4* __restrict__ src, float4* __restrict__ dst, int n4) {
    int i = blockIdx.x * 256 + threadIdx.x;
    if (i < n4) dst[i] = rtf4(src[i]);
}

// pack Wq|Wk|Wv -> [L][768][2304], tf32-rounded
__global__ void pack_qkv_kernel(const float4* __restrict__ q, const float4* __restrict__ k,
                                const float4* __restrict__ v, float4* __restrict__ dst, int n4) {
    int i = blockIdx.x * 256 + threadIdx.x;
    if (i >= n4) return;
    const int per = E_SZ * E_SZ / 4;       // f4 per matrix per layer
    const int rw  = E_SZ / 4;              // 192 f4 per row
    int l = i / per, r = i % per;
    int row = r / rw, c4 = r % rw;
    size_t base = (size_t)l * (E_SZ * QKV_LD / 4) + (size_t)row * (QKV_LD / 4) + c4;
    dst[base]          = rtf4(q[i]);
    dst[base + rw]     = rtf4(k[i]);
    dst[base + 2 * rw] = rtf4(v[i]);
}

// ---------------- Embedding ----------------
__global__ void embed_kernel(const int* __restrict__ tok,
                             const float* __restrict__ wte,
                             const float* __restrict__ wpe,
                             float* __restrict__ x) {
    int row = blockIdx.x;
    int t   = row % T_SZ;
    int tk  = tok[row];
    int e   = threadIdx.x * 4;
    const float4 a = *(const float4*)(wte + (size_t)tk * E_SZ + e);
    const float4 b = *(const float4*)(wpe + (size_t)t  * E_SZ + e);
    float4 o;
    o.x = a.x + b.x; o.y = a.y + b.y; o.z = a.z + b.z; o.w = a.w + b.w;
    *(float4*)(x + (size_t)row * E_SZ + e) = o;
}

// ---------------- LayerNorm (emits tf32-rounded output) ----------------
__global__ void layernorm_kernel(const float* __restrict__ x,
                                 const float* __restrict__ sc,
                                 const float* __restrict__ bi,
                                 float* __restrict__ out) {
    int row = blockIdx.x;
    const float* xr = x + (size_t)row * E_SZ;
    float lv[3];
    float s = 0.f, sq = 0.f;
#pragma unroll
    for (int i = 0; i < 3; i++) {
        float t = xr[threadIdx.x + i * 256];
        lv[i] = t; s += t; sq += t * t;
    }
#pragma unroll
    for (int o = 16; o > 0; o >>= 1) {
        s  += __shfl_down_sync(0xffffffffu, s,  o);
        sq += __shfl_down_sync(0xffffffffu, sq, o);
    }
    __shared__ float sa[8], sb[8];
    int w = threadIdx.x >> 5, lane = threadIdx.x & 31;
    if (lane == 0) { sa[w] = s; sb[w] = sq; }
    __syncthreads();
    __shared__ float s_mu, s_rstd;
    if (threadIdx.x == 0) {
        float ts = 0.f, tq = 0.f;
#pragma unroll
        for (int i = 0; i < 8; i++) { ts += sa[i]; tq += sb[i]; }
        float mu  = ts * (1.0f / E_SZ);
        float var = tq * (1.0f / E_SZ) - mu * mu;
        s_mu = mu;
        s_rstd = rsqrtf(var + 1e-5f);
    }
    __syncthreads();
    float mu = s_mu, rstd = s_rstd;
#pragma unroll
    for (int i = 0; i < 3; i++) {
        int c = threadIdx.x + i * 256;
        out[(size_t)row * E_SZ + c] = rtf((lv[i] - mu) * rstd * sc[c] + bi[c]);
    }
}

// ---------------- cp.async helpers ----------------
__device__ __forceinline__ void cp16(unsigned sdst, const void* src, bool pred) {
    int sz = pred ? 16 : 0;
    asm volatile("cp.async.cg.shared.global [%0], [%1], 16, %2;\n"
                 :: "r"(sdst), "l"(src), "r"(sz));
}
__device__ __forceinline__ void cp_commit() {
    asm volatile("cp.async.commit_group;\n");
}
__device__ __forceinline__ void cp_wait1() {
    asm volatile("cp.async.wait_group 1;\n");
}

// ---------------- TF32 tensor-core GEMM, cp.async 3-stage ----------------
__device__ __forceinline__ float gelu_exact(float v) {
    return 0.5f * v * (1.0f + erff(v * 0.70710678118654752f));
}
__device__ __forceinline__ void mma_tf32(float* d, const unsigned* a, const unsigned* b) {
    asm volatile(
        "mma.sync.aligned.m16n8k8.row.col.f32.tf32.tf32.f32 "
        "{%0,%1,%2,%3}, {%4,%5,%6,%7}, {%8,%9}, {%0,%1,%2,%3};"
        : "+f"(d[0]), "+f"(d[1]), "+f"(d[2]), "+f"(d[3])
        : "r"(a[0]), "r"(a[1]), "r"(a[2]), "r"(a[3]), "r"(b[0]), "r"(b[1]));
}

template <int BN, bool TRANSB, int EPI>
__device__ __forceinline__
void tgemm_dev(const float* __restrict__ A, const float* __restrict__ Bm,
               const float* __restrict__ bias, const float* __restrict__ resid,
               float* __restrict__ C, int N, int K, int bm, int bn) {
    constexpr int BK   = 16;
    constexpr int NJ   = BN / 16;
    constexpr int BROW = BN + 4;
    constexpr int ASZ  = 128 * 20;
    constexpr int BSZ  = TRANSB ? (BN * 20) : (BK * BROW);

    extern __shared__ unsigned smem_u[];
    unsigned* sA = smem_u;
    unsigned* sB = smem_u + 3 * ASZ;

    const int tid  = threadIdx.x;
    const int lane = tid & 31;
    const int wid  = tid >> 5;
    const int wm   = (wid & 3) * 32;
    const int wn   = (wid >> 2) * (BN / 2);
    const int g    = lane >> 2;
    const int t    = lane & 3;

    float acc[2][NJ][4];
#pragma unroll
    for (int i = 0; i < 2; i++)
#pragma unroll
        for (int j = 0; j < NJ; j++)
#pragma unroll
            for (int r = 0; r < 4; r++) acc[i][j][r] = 0.f;

    const int ar = tid >> 2;
    const int ak = (tid & 3) * 4;
    const int nbR = (BN == 128) ? (tid >> 5) : (tid >> 4);
    const int nbC = (BN == 128) ? ((tid & 31) * 4) : ((tid & 15) * 4);
    const int tbN = tid >> 2;
    const int tbK = (tid & 3) * 4;

    const unsigned sAaddr = (unsigned)__cvta_generic_to_shared(sA);
    const unsigned sBaddr = (unsigned)__cvta_generic_to_shared(sB);

    const int ntiles = K / BK;

    auto issue = [&](int st, int kt) {
        const int k0 = kt * BK;
        unsigned a_s = sAaddr + (st * ASZ) * 4;
        unsigned b_s = sBaddr + (st * BSZ) * 4;
        const float* ap = A + (size_t)(bm + ar) * K + k0 + ak;
        cp16(a_s + (ar * 20 + ak) * 4,        ap,                  true);
        cp16(a_s + ((ar + 64) * 20 + ak) * 4, ap + (size_t)64 * K, true);
        if (TRANSB) {
            int gn0 = bn + tbN;
            const float* bp0 = Bm + (size_t)(gn0 < N ? gn0 : 0) * K + k0 + tbK;
            cp16(b_s + (tbN * 20 + tbK) * 4, bp0, gn0 < N);
            if (BN == 128) {
                int gn1 = gn0 + 64;
                const float* bp1 = Bm + (size_t)(gn1 < N ? gn1 : 0) * K + k0 + tbK;
                cp16(b_s + ((tbN + 64) * 20 + tbK) * 4, bp1, gn1 < N);
            }
        } else {
            const float* bp = Bm + (size_t)(k0 + nbR) * N + bn + nbC;
            cp16(b_s + (nbR * BROW + nbC) * 4, bp, true);
            if (BN == 128)
                cp16(b_s + ((nbR + 8) * BROW + nbC) * 4, bp + (size_t)8 * N, true);
        }
    };

    issue(0, 0); cp_commit();
    issue(1, 1); cp_commit();

    for (int kt = 0; kt < ntiles; kt++) {
        cp_wait1();
        __syncthreads();
        const int cur = kt % 3;
        const unsigned* As = sA + cur * ASZ;
        const unsigned* Bs = sB + cur * BSZ;
#pragma unroll
        for (int ks = 0; ks < 2; ks++) {
            const int k8 = ks * 8;
            unsigned af[2][4], bf[NJ][2];
#pragma unroll
            for (int i = 0; i < 2; i++) {
                const int mr = wm + i * 16 + g;
                af[i][0] = As[mr * 20 + k8 + t];
                af[i][1] = As[(mr + 8) * 20 + k8 + t];
                af[i][2] = As[mr * 20 + k8 + t + 4];
                af[i][3] = As[(mr + 8) * 20 + k8 + t + 4];
            }
#pragma unroll
            for (int j = 0; j < NJ; j++) {
                const int nc = wn + j * 8 + g;
                if (TRANSB) {
                    bf[j][0] = Bs[nc * 20 + k8 + t];
                    bf[j][1] = Bs[nc * 20 + k8 + t + 4];
                } else {
                    bf[j][0] = Bs[(k8 + t) * BROW + nc];
                    bf[j][1] = Bs[(k8 + t + 4) * BROW + nc];
                }
            }
#pragma unroll
            for (int i = 0; i < 2; i++)
#pragma unroll
                for (int j = 0; j < NJ; j++)
                    mma_tf32(acc[i][j], af[i], bf[j]);
        }
        if (kt + 2 < ntiles) issue((kt + 2) % 3, kt + 2);
        cp_commit();
    }

    // ---- epilogue ----
#pragma unroll
    for (int i = 0; i < 2; i++) {
        const int r0 = bm + wm + i * 16 + g;
        const int r1 = r0 + 8;
#pragma unroll
        for (int j = 0; j < NJ; j++) {
            const int c = bn + wn + j * 8 + 2 * t;
            float v00 = acc[i][j][0], v01 = acc[i][j][1];
            float v10 = acc[i][j][2], v11 = acc[i][j][3];
            if (EPI & 1) {
                float bb0 = bias[c], bb1 = bias[c + 1];
                v00 += bb0; v01 += bb1; v10 += bb0; v11 += bb1;
            }
            if (EPI & 2) {
                v00 = gelu_exact(v00); v01 = gelu_exact(v01);
                v10 = gelu_exact(v10); v11 = gelu_exact(v11);
            }
            if (EPI & 4) {
                const float* rp0 = resid + (size_t)r0 * N + c;
                const float* rp1 = resid + (size_t)r1 * N + c;
                v00 += rp0[0]; v01 += rp0[1];
                v10 += rp1[0]; v11 += rp1[1];
            }
            if (EPI & 8) {
                v00 = rtf(v00); v01 = rtf(v01);
                v10 = rtf(v10); v11 = rtf(v11);
            }
            if (!TRANSB) {
                float2 p0; p0.x = v00; p0.y = v01;
                float2 p1; p1.x = v10; p1.y = v11;
                *(float2*)(C + (size_t)r0 * N + c) = p0;
                *(float2*)(C + (size_t)r1 * N + c) = p1;
            } else {
                // N may be odd (V=50257): scalar bounds-checked stores
                if (c < N)     { C[(size_t)r0 * N + c]     = v00; C[(size_t)r1 * N + c]     = v10; }
                if (c + 1 < N) { C[(size_t)r0 * N + c + 1] = v01; C[(size_t)r1 * N + c + 1] = v11; }
            }
        }
    }
}

template <int BN, bool TRANSB, int EPI>
__global__ __launch_bounds__(256)
void tgemm_k(const float* __restrict__ A, const float* __restrict__ Bm,
             const float* __restrict__ bias, const float* __restrict__ resid,
             float* __restrict__ C, int N, int K) {
    tgemm_dev<BN, TRANSB, EPI>(A, Bm, bias, resid, C, N, K,
                               blockIdx.x * 128, blockIdx.y * BN);
}

// smem bytes per instantiation (3 stages)
#define SM_G64F  (3 * (128 * 20 + 16 * 68) * 4)    // 43776
#define SM_G128F (3 * (128 * 20 + 16 * 132) * 4)   // 56064
#define SM_G128T (3 * (128 * 20 + 128 * 20) * 4)   // 61440

// ---------------- Causal attention: 128q flash tile, fp32 register GEMMs ---
// 256 threads (16x16): S tile 128x64 (8x4/thread), O tile 128x64 (8x4/thread)
#define ATTN_SMEM ((64 * 132 + 2 * 64 * 68 + 128 * 68 + 2 * 128) * 4)

__global__ __launch_bounds__(256, 2)
void attn_kernel(const float* __restrict__ qkv, float* __restrict__ o) {
    extern __shared__ float sm[];
    float (*Qs)[132] = (float(*)[132])sm;                       // [d][q]
    float (*Ks)[68]  = (float(*)[68])(sm + 64 * 132);           // [d][k]
    float (*Vs)[68]  = (float(*)[68])(sm + 64 * 132 + 64 * 68); // [k][d]
    float (*Ss)[68]  = (float(*)[68])(sm + 64 * 132 + 2 * 64 * 68); // [q][k]
    float* ms = sm + 64 * 132 + 2 * 64 * 68 + 128 * 68;
    float* ls = ms + 128;

    const int bh  = blockIdx.y;
    const int b   = bh / H_SZ, h = bh % H_SZ;
    const int q0  = blockIdx.x * 128;
    const int tid = threadIdx.x;
    const int tx  = tid & 15, ty = tid >> 4;

    const float* qb = qkv + h * D_SZ;
    const float* kb = qkv + E_SZ + h * D_SZ;
    const float* vb = qkv + 2 * E_SZ + h * D_SZ;

    // Q transposed + pre-scaled: 128 rows x 64 d
#pragma unroll
    for (int i = 0; i < 8; i++) {
        int f  = tid + i * 256;
        int qq = f & 127, d4 = (f >> 7) * 4;
        float4 t = *(const float4*)(qb + (size_t)(b * T_SZ + q0 + qq) * QKV_LD + d4);
        Qs[d4+0][qq] = t.x * 0.125f; Qs[d4+1][qq] = t.y * 0.125f;
        Qs[d4+2][qq] = t.z * 0.125f; Qs[d4+3][qq] = t.w * 0.125f;
    }
    if (tid < 128) { ms[tid] = -1e30f; ls[tid] = 0.f; }

    float acc[8][4];
#pragma unroll
    for (int r = 0; r < 8; r++)
#pragma unroll
        for (int c = 0; c < 4; c++) acc[r][c] = 0.f;

    for (int kt = 0; kt <= q0 + 64; kt += 64) {
        // K transposed
#pragma unroll
        for (int i = 0; i < 4; i++) {
            int f  = tid + i * 256;
            int kk = f & 63, d4 = (f >> 6) * 4;
            float4 t = *(const float4*)(kb + (size_t)(b * T_SZ + kt + kk) * QKV_LD + d4);
            Ks[d4+0][kk] = t.x; Ks[d4+1][kk] = t.y;
            Ks[d4+2][kk] = t.z; Ks[d4+3][kk] = t.w;
        }
        // V natural
#pragma unroll
        for (int i = 0; i < 4; i++) {
            int f  = tid + i * 256;
            int kk = f >> 4, d4 = (f & 15) * 4;
            *(float4*)&Vs[kk][d4] =
                *(const float4*)(vb + (size_t)(b * T_SZ + kt + kk) * QKV_LD + d4);
        }
        __syncthreads();

        // ---- S = Q K^T (8x4 per thread) ----
        float s[8][4];
#pragma unroll
        for (int r = 0; r < 8; r++)
#pragma unroll
            for (int c = 0; c < 4; c++) s[r][c] = 0.f;
#pragma unroll 2
        for (int d = 0; d < 64; d++) {
            float4 a0 = *(const float4*)&Qs[d][8 * ty];
            float4 a1 = *(const float4*)&Qs[d][8 * ty + 4];
            float4 bk = *(const float4*)&Ks[d][4 * tx];
            float a[8] = {a0.x, a0.y, a0.z, a0.w, a1.x, a1.y, a1.z, a1.w};
            float bb[4] = {bk.x, bk.y, bk.z, bk.w};
#pragma unroll
            for (int r = 0; r < 8; r++)
#pragma unroll
                for (int c = 0; c < 4; c++) s[r][c] += a[r] * bb[c];
        }
        // causal mask (only last two tiles can intersect the diagonal)
        if (kt >= q0) {
#pragma unroll
            for (int r = 0; r < 8; r++)
#pragma unroll
                for (int c = 0; c < 4; c++)
                    if (kt + 4 * tx + c > q0 + 8 * ty + r) s[r][c] = -1e30f;
        }

        // ---- online softmax (row = half-warp of 16 lanes) ----
        float cfl[8];
#pragma unroll
        for (int r = 0; r < 8; r++) {
            const int row = 8 * ty + r;
            float mx = fmaxf(fmaxf(s[r][0], s[r][1]), fmaxf(s[r][2], s[r][3]));
#pragma unroll
            for (int off = 1; off < 16; off <<= 1)
                mx = fmaxf(mx, __shfl_xor_sync(0xffffffffu, mx, off));
            const float mold = ms[row];
            const float mnew = fmaxf(mold, mx);
            float ps = 0.f;
#pragma unroll
            for (int c = 0; c < 4; c++) {
                float p = __expf(s[r][c] - mnew);
                Ss[row][4 * tx + c] = p;
                ps += p;
            }
#pragma unroll
            for (int off = 1; off < 16; off <<= 1)
                ps += __shfl_xor_sync(0xffffffffu, ps, off);
            cfl[r] = __expf(mold - mnew);
            if (tx == 0) { ms[row] = mnew; ls[row] = ls[row] * cfl[r] + ps; }
        }
        __syncwarp();   // Ss rows are half-warp-local; warp sync suffices

        // ---- O = O*cf + P V ----
#pragma unroll
        for (int r = 0; r < 8; r++)
#pragma unroll
            for (int c = 0; c < 4; c++) acc[r][c] *= cfl[r];
#pragma unroll 4
        for (int kk = 0; kk < 64; kk++) {
            float4 vv = *(const float4*)&Vs[kk][4 * tx];
#pragma unroll
            for (int r = 0; r < 8; r++) {
                float p = Ss[8 * ty + r][kk];
                acc[r][0] += p * vv.x; acc[r][1] += p * vv.y;
                acc[r][2] += p * vv.z; acc[r][3] += p * vv.w;
            }
        }
        __syncthreads();
    }

    // ---- epilogue: tf32-rounded (A operand of Wo GEMM) ----
#pragma unroll
    for (int r = 0; r < 8; r++) {
        const float inv = 1.f / ls[8 * ty + r];
        float4 t;
        t.x = rtf(acc[r][0] * inv); t.y = rtf(acc[r][1] * inv);
        t.z = rtf(acc[r][2] * inv); t.w = rtf(acc[r][3] * inv);
        *(float4*)(o + (size_t)(b * T_SZ + q0 + 8 * ty + r) * E_SZ + h * D_SZ + 4 * tx) = t;
    }
}

// ---------------- Host orchestration ----------------
extern "C" void kernel_launch(void* const* d_in, const int* in_sizes, int n_in,
                              void* d_out, int out_size) {
    (void)in_sizes; (void)n_in; (void)out_size;
    const int*   tokens = (const int*)  d_in[0];
    const float* wte    = (const float*)d_in[1];
    const float* wpe    = (const float*)d_in[2];
    const float* Wq     = (const float*)d_in[3];
    const float* Wk     = (const float*)d_in[4];
    const float* Wv     = (const float*)d_in[5];
    const float* Wo     = (const float*)d_in[6];
    const float* bo     = (const float*)d_in[7];
    const float* ln1_s  = (const float*)d_in[8];
    const float* ln1_b  = (const float*)d_in[9];
    const float* W1     = (const float*)d_in[10];
    const float* b1     = (const float*)d_in[11];
    const float* W2     = (const float*)d_in[12];
    const float* b2     = (const float*)d_in[13];
    const float* ln2_s  = (const float*)d_in[14];
    const float* ln2_b  = (const float*)d_in[15];
    const float* lnf_s  = (const float*)d_in[16];
    const float* lnf_b  = (const float*)d_in[17];
    float* out = (float*)d_out;

    float *x, *h, *qkv, *att, *m1;
    float *wqkv, *wo, *w1, *w2, *wt;
    cudaGetSymbolAddress((void**)&x,    g_x);
    cudaGetSymbolAddress((void**)&h,    g_h);
    cudaGetSymbolAddress((void**)&qkv,  g_qkv);
    cudaGetSymbolAddress((void**)&att,  g_att);
    cudaGetSymbolAddress((void**)&m1,   g_m1);
    cudaGetSymbolAddress((void**)&wqkv, g_wqkv);
    cudaGetSymbolAddress((void**)&wo,   g_wo);
    cudaGetSymbolAddress((void**)&w1,   g_w1);
    cudaGetSymbolAddress((void**)&w2,   g_w2);
    cudaGetSymbolAddress((void**)&wt,   g_wte);

    cudaFuncSetAttribute(attn_kernel,
                         cudaFuncAttributeMaxDynamicSharedMemorySize, ATTN_SMEM);
    cudaFuncSetAttribute(tgemm_k<64, false, 5>,
                         cudaFuncAttributeMaxDynamicSharedMemorySize, SM_G64F);
    cudaFuncSetAttribute(tgemm_k<128, false, 0>,
                         cudaFuncAttributeMaxDynamicSharedMemorySize, SM_G128F);
    cudaFuncSetAttribute(tgemm_k<128, false, 11>,
                         cudaFuncAttributeMaxDynamicSharedMemorySize, SM_G128F);
    cudaFuncSetAttribute(tgemm_k<128, true, 0>,
                         cudaFuncAttributeMaxDynamicSharedMemorySize, SM_G128T);

    // ---- per-launch weight rounding / packing ----
    {
        const int nE = L_SZ * E_SZ * E_SZ / 4;   // 884736
        const int nF = L_SZ * E_SZ * FF / 4;     // 3538944
        const int nV = V_SZ * E_SZ / 4;          // 9649344
        pack_qkv_kernel<<<(nE + 255) / 256, 256>>>(
            (const float4*)Wq, (const float4*)Wk, (const float4*)Wv, (float4*)wqkv, nE);
        cvt_kernel<<<(nE + 255) / 256, 256>>>((const float4*)Wo, (float4*)wo, nE);
        cvt_kernel<<<(nF + 255) / 256, 256>>>((const float4*)W1, (float4*)w1, nF);
        cvt_kernel<<<(nF + 255) / 256, 256>>>((const float4*)W2, (float4*)w2, nF);
        cvt_kernel<<<(nV + 255) / 256, 256>>>((const float4*)wte, (float4*)wt, nV);
    }

    embed_kernel<<<BT, 192>>>(tokens, wte, wpe, x);

    const dim3 gE(BT / 128, E_SZ / 64);            // 16 x 12
    const dim3 gQKV(BT / 128, QKV_LD / 128);       // 16 x 18
    const dim3 gF(BT / 128, FF / 128);             // 16 x 24
    const dim3 gATT(T_SZ / 128, B_SZ * H_SZ);      // 8 x 24
    const dim3 gLOG(BT / 128, (V_SZ + 127) / 128); // 16 x 393

    for (int l = 0; l < L_SZ; l++) {
        const size_t wqOff = (size_t)l * E_SZ * QKV_LD;
        const size_t wOff  = (size_t)l * E_SZ * E_SZ;
        const size_t w1Off = (size_t)l * E_SZ * FF;
        const size_t vOff  = (size_t)l * E_SZ;
        const size_t fOff  = (size_t)l * FF;

        layernorm_kernel<<<BT, 256>>>(x, ln1_s + vOff, ln1_b + vOff, h);
        tgemm_k<128, false, 0><<<gQKV, 256, SM_G128F>>>(h, wqkv + wqOff, nullptr, nullptr,
                                                        qkv, QKV_LD, E_SZ);
        attn_kernel<<<gATT, 256, ATTN_SMEM>>>(qkv, att);
        tgemm_k<64, false, 5><<<gE, 256, SM_G64F>>>(att, wo + wOff, bo + vOff, x, x, E_SZ, E_SZ);
        layernorm_kernel<<<BT, 256>>>(x, ln2_s + vOff, ln2_b + vOff, h);
        tgemm_k<128, false, 11><<<gF, 256, SM_G128F>>>(h, w1 + w1Off, b1 + fOff, nullptr, m1, FF, E_SZ);
        tgemm_k<64, false, 5><<<gE, 256, SM_G64F>>>(m1, w2 + w1Off, b2 + vOff, x, x, E_SZ, FF);
    }

    layernorm_kernel<<<BT, 256>>>(x, lnf_s, lnf_b, h);
    tgemm_k<128, true, 0><<<gLOG, 256, SM_G128T>>>(h, wt, nullptr, nullptr, out, V_SZ, E_SZ);
}

// round 10
// speedup vs baseline: 1.0752x; 1.0752x over previous
#include <cuda_runtime.h>
#include <cuda_bf16.h>
#include <math.h>

// ---------------- Problem constants ----------------
#define V_SZ 50257
#define E_SZ 768
#define H_SZ 12
#define L_SZ 6
#define T_SZ 1024
#define B_SZ 2
#define D_SZ 64
#define BT   (B_SZ * T_SZ)      // 2048
#define FF   (4 * E_SZ)         // 3072
#define QKV_LD (3 * E_SZ)       // 2304

// ---------------- Scratch (device globals; no allocations allowed) ----------
__device__ float g_x   [BT * E_SZ];
__device__ float g_h   [BT * E_SZ];
__device__ float g_qkv [BT * QKV_LD];
__device__ float g_att [BT * E_SZ];
__device__ float g_m1  [BT * FF];
// tf32-rounded weight copies
__device__ float g_wqkv[L_SZ * E_SZ * QKV_LD];
__device__ float g_wo  [L_SZ * E_SZ * E_SZ];
__device__ float g_w1  [L_SZ * E_SZ * FF];
__device__ float g_w2  [L_SZ * E_SZ * FF];
__device__ float g_wte [V_SZ * E_SZ];

// ---------------- tf32 helpers ----------------
__device__ __forceinline__ unsigned f2tf(float f) {
    unsigned u;
    asm("cvt.rna.tf32.f32 %0, %1;" : "=r"(u) : "f"(f));
    return u;
}
__device__ __forceinline__ float rtf(float f) { return __uint_as_float(f2tf(f)); }
__device__ __forceinline__ float4 rtf4(float4 v) {
    v.x = rtf(v.x); v.y = rtf(v.y); v.z = rtf(v.z); v.w = rtf(v.w);
    return v;
}

// round-convert fp32 array to tf32-representable fp32
__global__ void cvt_kernel(const float4* __restrict__ src, float4* __restrict__ dst, int n4) {
    int i = blockIdx.x * 256 + threadIdx.x;
    if (i < n4) dst[i] = rtf4(src[i]);
}

// pack Wq|Wk|Wv -> [L][768][2304], tf32-rounded
__global__ void pack_qkv_kernel(const float4* __restrict__ q, const float4* __restrict__ k,
                                const float4* __restrict__ v, float4* __restrict__ dst, int n4) {
    int i = blockIdx.x * 256 + threadIdx.x;
    if (i >= n4) return;
    const int per = E_SZ * E_SZ / 4;       // f4 per matrix per layer
    const int rw  = E_SZ / 4;              // 192 f4 per row
    int l = i / per, r = i % per;
    int row = r / rw, c4 = r % rw;
    size_t base = (size_t)l * (E_SZ * QKV_LD / 4) + (size_t)row * (QKV_LD / 4) + c4;
    dst[base]          = rtf4(q[i]);
    dst[base + rw]     = rtf4(k[i]);
    dst[base + 2 * rw] = rtf4(v[i]);
}

// ---------------- Embedding ----------------
__global__ void embed_kernel(const int* __restrict__ tok,
                             const float* __restrict__ wte,
                             const float* __restrict__ wpe,
                             float* __restrict__ x) {
    int row = blockIdx.x;
    int t   = row % T_SZ;
    int tk  = tok[row];
    int e   = threadIdx.x * 4;
    const float4 a = *(const float4*)(wte + (size_t)tk * E_SZ + e);
    const float4 b = *(const float4*)(wpe + (size_t)t  * E_SZ + e);
    float4 o;
    o.x = a.x + b.x; o.y = a.y + b.y; o.z = a.z + b.z; o.w = a.w + b.w;
    *(float4*)(x + (size_t)row * E_SZ + e) = o;
}

// ---------------- LayerNorm (emits tf32-rounded output) ----------------
__global__ void layernorm_kernel(const float* __restrict__ x,
                                 const float* __restrict__ sc,
                                 const float* __restrict__ bi,
                                 float* __restrict__ out) {
    int row = blockIdx.x;
    const float* xr = x + (size_t)row * E_SZ;
    float lv[3];
    float s = 0.f, sq = 0.f;
#pragma unroll
    for (int i = 0; i < 3; i++) {
        float t = xr[threadIdx.x + i * 256];
        lv[i] = t; s += t; sq += t * t;
    }
#pragma unroll
    for (int o = 16; o > 0; o >>= 1) {
        s  += __shfl_down_sync(0xffffffffu, s,  o);
        sq += __shfl_down_sync(0xffffffffu, sq, o);
    }
    __shared__ float sa[8], sb[8];
    int w = threadIdx.x >> 5, lane = threadIdx.x & 31;
    if (lane == 0) { sa[w] = s; sb[w] = sq; }
    __syncthreads();
    __shared__ float s_mu, s_rstd;
    if (threadIdx.x == 0) {
        float ts = 0.f, tq = 0.f;
#pragma unroll
        for (int i = 0; i < 8; i++) { ts += sa[i]; tq += sb[i]; }
        float mu  = ts * (1.0f / E_SZ);
        float var = tq * (1.0f / E_SZ) - mu * mu;
        s_mu = mu;
        s_rstd = rsqrtf(var + 1e-5f);
    }
    __syncthreads();
    float mu = s_mu, rstd = s_rstd;
#pragma unroll
    for (int i = 0; i < 3; i++) {
        int c = threadIdx.x + i * 256;
        out[(size_t)row * E_SZ + c] = rtf((lv[i] - mu) * rstd * sc[c] + bi[c]);
    }
}

// ---------------- cp.async helpers ----------------
__device__ __forceinline__ void cp16(unsigned sdst, const void* src, bool pred) {
    int sz = pred ? 16 : 0;
    asm volatile("cp.async.cg.shared.global [%0], [%1], 16, %2;\n"
                 :: "r"(sdst), "l"(src), "r"(sz));
}
__device__ __forceinline__ void cp_commit() {
    asm volatile("cp.async.commit_group;\n");
}
__device__ __forceinline__ void cp_wait1() {
    asm volatile("cp.async.wait_group 1;\n");
}

// ---------------- TF32 tensor-core GEMM, cp.async 3-stage ----------------
__device__ __forceinline__ float gelu_exact(float v) {
    return 0.5f * v * (1.0f + erff(v * 0.70710678118654752f));
}
__device__ __forceinline__ void mma_tf32(float* d, const unsigned* a, const unsigned* b) {
    asm volatile(
        "mma.sync.aligned.m16n8k8.row.col.f32.tf32.tf32.f32 "
        "{%0,%1,%2,%3}, {%4,%5,%6,%7}, {%8,%9}, {%0,%1,%2,%3};"
        : "+f"(d[0]), "+f"(d[1]), "+f"(d[2]), "+f"(d[3])
        : "r"(a[0]), "r"(a[1]), "r"(a[2]), "r"(a[3]), "r"(b[0]), "r"(b[1]));
}

template <int BN, bool TRANSB, int EPI>
__device__ __forceinline__
void tgemm_dev(const float* __restrict__ A, const float* __restrict__ Bm,
               const float* __restrict__ bias, const float* __restrict__ resid,
               float* __restrict__ C, int N, int K, int bm, int bn) {
    constexpr int BK   = 16;
    constexpr int NJ   = BN / 16;
    constexpr int BROW = BN + 4;
    constexpr int ASZ  = 128 * 20;
    constexpr int BSZ  = TRANSB ? (BN * 20) : (BK * BROW);

    extern __shared__ unsigned smem_u[];
    unsigned* sA = smem_u;
    unsigned* sB = smem_u + 3 * ASZ;

    const int tid  = threadIdx.x;
    const int lane = tid & 31;
    const int wid  = tid >> 5;
    const int wm   = (wid & 3) * 32;
    const int wn   = (wid >> 2) * (BN / 2);
    const int g    = lane >> 2;
    const int t    = lane & 3;

    float acc[2][NJ][4];
#pragma unroll
    for (int i = 0; i < 2; i++)
#pragma unroll
        for (int j = 0; j < NJ; j++)
#pragma unroll
            for (int r = 0; r < 4; r++) acc[i][j][r] = 0.f;

    const int ar = tid >> 2;
    const int ak = (tid & 3) * 4;
    const int nbR = (BN == 128) ? (tid >> 5) : (tid >> 4);
    const int nbC = (BN == 128) ? ((tid & 31) * 4) : ((tid & 15) * 4);
    const int tbN = tid >> 2;
    const int tbK = (tid & 3) * 4;

    const unsigned sAaddr = (unsigned)__cvta_generic_to_shared(sA);
    const unsigned sBaddr = (unsigned)__cvta_generic_to_shared(sB);

    const int ntiles = K / BK;

    auto issue = [&](int st, int kt) {
        const int k0 = kt * BK;
        unsigned a_s = sAaddr + (st * ASZ) * 4;
        unsigned b_s = sBaddr + (st * BSZ) * 4;
        const float* ap = A + (size_t)(bm + ar) * K + k0 + ak;
        cp16(a_s + (ar * 20 + ak) * 4,        ap,                  true);
        cp16(a_s + ((ar + 64) * 20 + ak) * 4, ap + (size_t)64 * K, true);
        if (TRANSB) {
            int gn0 = bn + tbN;
            const float* bp0 = Bm + (size_t)(gn0 < N ? gn0 : 0) * K + k0 + tbK;
            cp16(b_s + (tbN * 20 + tbK) * 4, bp0, gn0 < N);
            if (BN == 128) {
                int gn1 = gn0 + 64;
                const float* bp1 = Bm + (size_t)(gn1 < N ? gn1 : 0) * K + k0 + tbK;
                cp16(b_s + ((tbN + 64) * 20 + tbK) * 4, bp1, gn1 < N);
            }
        } else {
            const float* bp = Bm + (size_t)(k0 + nbR) * N + bn + nbC;
            cp16(b_s + (nbR * BROW + nbC) * 4, bp, true);
            if (BN == 128)
                cp16(b_s + ((nbR + 8) * BROW + nbC) * 4, bp + (size_t)8 * N, true);
        }
    };

    issue(0, 0); cp_commit();
    issue(1, 1); cp_commit();

    for (int kt = 0; kt < ntiles; kt++) {
        cp_wait1();
        __syncthreads();
        const int cur = kt % 3;
        const unsigned* As = sA + cur * ASZ;
        const unsigned* Bs = sB + cur * BSZ;
#pragma unroll
        for (int ks = 0; ks < 2; ks++) {
            const int k8 = ks * 8;
            unsigned af[2][4], bf[NJ][2];
#pragma unroll
            for (int i = 0; i < 2; i++) {
                const int mr = wm + i * 16 + g;
                af[i][0] = As[mr * 20 + k8 + t];
                af[i][1] = As[(mr + 8) * 20 + k8 + t];
                af[i][2] = As[mr * 20 + k8 + t + 4];
                af[i][3] = As[(mr + 8) * 20 + k8 + t + 4];
            }
#pragma unroll
            for (int j = 0; j < NJ; j++) {
                const int nc = wn + j * 8 + g;
                if (TRANSB) {
                    bf[j][0] = Bs[nc * 20 + k8 + t];
                    bf[j][1] = Bs[nc * 20 + k8 + t + 4];
                } else {
                    bf[j][0] = Bs[(k8 + t) * BROW + nc];
                    bf[j][1] = Bs[(k8 + t + 4) * BROW + nc];
                }
            }
#pragma unroll
            for (int i = 0; i < 2; i++)
#pragma unroll
                for (int j = 0; j < NJ; j++)
                    mma_tf32(acc[i][j], af[i], bf[j]);
        }
        if (kt + 2 < ntiles) issue((kt + 2) % 3, kt + 2);
        cp_commit();
    }

    // ---- epilogue ----
#pragma unroll
    for (int i = 0; i < 2; i++) {
        const int r0 = bm + wm + i * 16 + g;
        const int r1 = r0 + 8;
#pragma unroll
        for (int j = 0; j < NJ; j++) {
            const int c = bn + wn + j * 8 + 2 * t;
            float v00 = acc[i][j][0], v01 = acc[i][j][1];
            float v10 = acc[i][j][2], v11 = acc[i][j][3];
            if (EPI & 1) {
                float bb0 = bias[c], bb1 = bias[c + 1];
                v00 += bb0; v01 += bb1; v10 += bb0; v11 += bb1;
            }
            if (EPI & 2) {
                v00 = gelu_exact(v00); v01 = gelu_exact(v01);
                v10 = gelu_exact(v10); v11 = gelu_exact(v11);
            }
            if (EPI & 4) {
                const float* rp0 = resid + (size_t)r0 * N + c;
                const float* rp1 = resid + (size_t)r1 * N + c;
                v00 += rp0[0]; v01 += rp0[1];
                v10 += rp1[0]; v11 += rp1[1];
            }
            if (EPI & 8) {
                v00 = rtf(v00); v01 = rtf(v01);
                v10 = rtf(v10); v11 = rtf(v11);
            }
            if (!TRANSB) {
                float2 p0; p0.x = v00; p0.y = v01;
                float2 p1; p1.x = v10; p1.y = v11;
                *(float2*)(C + (size_t)r0 * N + c) = p0;
                *(float2*)(C + (size_t)r1 * N + c) = p1;
            } else {
                // N may be odd (V=50257): scalar bounds-checked stores
                if (c < N)     { C[(size_t)r0 * N + c]     = v00; C[(size_t)r1 * N + c]     = v10; }
                if (c + 1 < N) { C[(size_t)r0 * N + c + 1] = v01; C[(size_t)r1 * N + c + 1] = v11; }
            }
        }
    }
}

template <int BN, bool TRANSB, int EPI>
__global__ __launch_bounds__(256)
void tgemm_k(const float* __restrict__ A, const float* __restrict__ Bm,
             const float* __restrict__ bias, const float* __restrict__ resid,
             float* __restrict__ C, int N, int K) {
    tgemm_dev<BN, TRANSB, EPI>(A, Bm, bias, resid, C, N, K,
                               blockIdx.x * 128, blockIdx.y * BN);
}

// smem bytes per instantiation (3 stages)
#define SM_G64F  (3 * (128 * 20 + 16 * 68) * 4)    // 43776
#define SM_G128F (3 * (128 * 20 + 16 * 132) * 4)   // 56064
#define SM_G128T (3 * (128 * 20 + 128 * 20) * 4)   // 61440

// ---------------- Causal attention: 64q flash tile (round-8 design) --------
// reads q/k/v from packed qkv buffer with row stride QKV_LD
#define ATTN_SMEM (4 * 64 * 68 * 4 + 2 * 64 * 4)

__global__ __launch_bounds__(256)
void attn_kernel(const float* __restrict__ qkv, float* __restrict__ o) {
    extern __shared__ float sm[];
    float (*Qs)[68] = (float(*)[68])sm;                  // [d][q]
    float (*Ks)[68] = (float(*)[68])(sm + 64 * 68);      // [d][k]
    float (*Vs)[68] = (float(*)[68])(sm + 2 * 64 * 68);  // [k][d]
    float (*Ss)[68] = (float(*)[68])(sm + 3 * 64 * 68);  // [q][k]
    float* ms = sm + 4 * 64 * 68;
    float* ls = ms + 64;

    const int bh  = blockIdx.y;
    const int b   = bh / H_SZ, h = bh % H_SZ;
    const int q0  = blockIdx.x * 64;
    const int tid = threadIdx.x;
    const int tx  = tid & 15, ty = tid >> 4;

    const float* qb = qkv + h * D_SZ;
    const float* kb = qkv + E_SZ + h * D_SZ;
    const float* vb = qkv + 2 * E_SZ + h * D_SZ;

#pragma unroll
    for (int i = 0; i < 4; i++) {
        int f  = tid + i * 256;
        int qq = f & 63, d4 = (f >> 6) * 4;
        float4 t = *(const float4*)(qb + (size_t)(b * T_SZ + q0 + qq) * QKV_LD + d4);
        Qs[d4+0][qq] = t.x * 0.125f; Qs[d4+1][qq] = t.y * 0.125f;
        Qs[d4+2][qq] = t.z * 0.125f; Qs[d4+3][qq] = t.w * 0.125f;
    }
    if (tid < 64) { ms[tid] = -1e30f; ls[tid] = 0.f; }

    float acc[4][4];
#pragma unroll
    for (int r = 0; r < 4; r++)
#pragma unroll
        for (int c = 0; c < 4; c++) acc[r][c] = 0.f;

    for (int kt = 0; kt <= q0; kt += 64) {
#pragma unroll
        for (int i = 0; i < 4; i++) {
            int f  = tid + i * 256;
            int kk = f & 63, d4 = (f >> 6) * 4;
            float4 t = *(const float4*)(kb + (size_t)(b * T_SZ + kt + kk) * QKV_LD + d4);
            Ks[d4+0][kk] = t.x; Ks[d4+1][kk] = t.y;
            Ks[d4+2][kk] = t.z; Ks[d4+3][kk] = t.w;
        }
#pragma unroll
        for (int i = 0; i < 4; i++) {
            int f  = tid + i * 256;
            int kk = f >> 4, d4 = (f & 15) * 4;
            *(float4*)&Vs[kk][d4] =
                *(const float4*)(vb + (size_t)(b * T_SZ + kt + kk) * QKV_LD + d4);
        }
        __syncthreads();

        // ---- S = Q K^T ----
        float s[4][4];
#pragma unroll
        for (int r = 0; r < 4; r++)
#pragma unroll
            for (int c = 0; c < 4; c++) s[r][c] = 0.f;
#pragma unroll 4
        for (int d = 0; d < 64; d++) {
            float4 aq = *(const float4*)&Qs[d][4 * ty];
            float4 bk = *(const float4*)&Ks[d][4 * tx];
            float a[4] = {aq.x, aq.y, aq.z, aq.w};
            float bb[4] = {bk.x, bk.y, bk.z, bk.w};
#pragma unroll
            for (int r = 0; r < 4; r++)
#pragma unroll
                for (int c = 0; c < 4; c++) s[r][c] += a[r] * bb[c];
        }

        // ---- softmax (row = half-warp) ----
        const bool diag = (kt == q0);
        float cfl[4];
#pragma unroll
        for (int r = 0; r < 4; r++) {
            const int row = 4 * ty + r;
            if (diag) {
#pragma unroll
                for (int c = 0; c < 4; c++)
                    if (4 * tx + c > row) s[r][c] = -1e30f;
            }
            float mx = fmaxf(fmaxf(s[r][0], s[r][1]), fmaxf(s[r][2], s[r][3]));
#pragma unroll
            for (int off = 1; off < 16; off <<= 1)
                mx = fmaxf(mx, __shfl_xor_sync(0xffffffffu, mx, off));
            const float mold = ms[row];
            const float mnew = fmaxf(mold, mx);
            float ps = 0.f;
#pragma unroll
            for (int c = 0; c < 4; c++) {
                float p = __expf(s[r][c] - mnew);
                Ss[row][4 * tx + c] = p;
                ps += p;
            }
#pragma unroll
            for (int off = 1; off < 16; off <<= 1)
                ps += __shfl_xor_sync(0xffffffffu, ps, off);
            cfl[r] = __expf(mold - mnew);
            if (tx == 0) { ms[row] = mnew; ls[row] = ls[row] * cfl[r] + ps; }
        }
        __syncwarp();

        // ---- O = O*cf + P V ----
#pragma unroll
        for (int r = 0; r < 4; r++)
#pragma unroll
            for (int c = 0; c < 4; c++) acc[r][c] *= cfl[r];
#pragma unroll 4
        for (int kk = 0; kk < 64; kk++) {
            float4 vv = *(const float4*)&Vs[kk][4 * tx];
#pragma unroll
            for (int r = 0; r < 4; r++) {
                float p = Ss[4 * ty + r][kk];
                acc[r][0] += p * vv.x; acc[r][1] += p * vv.y;
                acc[r][2] += p * vv.z; acc[r][3] += p * vv.w;
            }
        }
        __syncthreads();
    }

    // ---- epilogue: tf32-rounded (A operand of Wo GEMM) ----
#pragma unroll
    for (int r = 0; r < 4; r++) {
        const float inv = 1.f / ls[4 * ty + r];
        float4 t;
        t.x = rtf(acc[r][0] * inv); t.y = rtf(acc[r][1] * inv);
        t.z = rtf(acc[r][2] * inv); t.w = rtf(acc[r][3] * inv);
        *(float4*)(o + (size_t)(b * T_SZ + q0 + 4 * ty + r) * E_SZ + h * D_SZ + 4 * tx) = t;
    }
}

// ---------------- Host orchestration ----------------
extern "C" void kernel_launch(void* const* d_in, const int* in_sizes, int n_in,
                              void* d_out, int out_size) {
    (void)in_sizes; (void)n_in; (void)out_size;
    const int*   tokens = (const int*)  d_in[0];
    const float* wte    = (const float*)d_in[1];
    const float* wpe    = (const float*)d_in[2];
    const float* Wq     = (const float*)d_in[3];
    const float* Wk     = (const float*)d_in[4];
    const float* Wv     = (const float*)d_in[5];
    const float* Wo     = (const float*)d_in[6];
    const float* bo     = (const float*)d_in[7];
    const float* ln1_s  = (const float*)d_in[8];
    const float* ln1_b  = (const float*)d_in[9];
    const float* W1     = (const float*)d_in[10];
    const float* b1     = (const float*)d_in[11];
    const float* W2     = (const float*)d_in[12];
    const float* b2     = (const float*)d_in[13];
    const float* ln2_s  = (const float*)d_in[14];
    const float* ln2_b  = (const float*)d_in[15];
    const float* lnf_s  = (const float*)d_in[16];
    const float* lnf_b  = (const float*)d_in[17];
    float* out = (float*)d_out;

    float *x, *h, *qkv, *att, *m1;
    float *wqkv, *wo, *w1, *w2, *wt;
    cudaGetSymbolAddress((void**)&x,    g_x);
    cudaGetSymbolAddress((void**)&h,    g_h);
    cudaGetSymbolAddress((void**)&qkv,  g_qkv);
    cudaGetSymbolAddress((void**)&att,  g_att);
    cudaGetSymbolAddress((void**)&m1,   g_m1);
    cudaGetSymbolAddress((void**)&wqkv, g_wqkv);
    cudaGetSymbolAddress((void**)&wo,   g_wo);
    cudaGetSymbolAddress((void**)&w1,   g_w1);
    cudaGetSymbolAddress((void**)&w2,   g_w2);
    cudaGetSymbolAddress((void**)&wt,   g_wte);

    cudaFuncSetAttribute(attn_kernel,
                         cudaFuncAttributeMaxDynamicSharedMemorySize, ATTN_SMEM);
    cudaFuncSetAttribute(tgemm_k<64, false, 5>,
                         cudaFuncAttributeMaxDynamicSharedMemorySize, SM_G64F);
    cudaFuncSetAttribute(tgemm_k<128, false, 0>,
                         cudaFuncAttributeMaxDynamicSharedMemorySize, SM_G128F);
    cudaFuncSetAttribute(tgemm_k<128, false, 11>,
                         cudaFuncAttributeMaxDynamicSharedMemorySize, SM_G128F);
    cudaFuncSetAttribute(tgemm_k<128, true, 0>,
                         cudaFuncAttributeMaxDynamicSharedMemorySize, SM_G128T);

    // ---- per-launch weight rounding / packing ----
    {
        const int nE = L_SZ * E_SZ * E_SZ / 4;   // 884736
        const int nF = L_SZ * E_SZ * FF / 4;     // 3538944
        const int nV = V_SZ * E_SZ / 4;          // 9649344
        pack_qkv_kernel<<<(nE + 255) / 256, 256>>>(
            (const float4*)Wq, (const float4*)Wk, (const float4*)Wv, (float4*)wqkv, nE);
        cvt_kernel<<<(nE + 255) / 256, 256>>>((const float4*)Wo, (float4*)wo, nE);
        cvt_kernel<<<(nF + 255) / 256, 256>>>((const float4*)W1, (float4*)w1, nF);
        cvt_kernel<<<(nF + 255) / 256, 256>>>((const float4*)W2, (float4*)w2, nF);
        cvt_kernel<<<(nV + 255) / 256, 256>>>((const float4*)wte, (float4*)wt, nV);
    }

    embed_kernel<<<BT, 192>>>(tokens, wte, wpe, x);

    const dim3 gE(BT / 128, E_SZ / 64);            // 16 x 12
    const dim3 gQKV(BT / 128, QKV_LD / 128);       // 16 x 18
    const dim3 gF(BT / 128, FF / 128);             // 16 x 24
    const dim3 gATT(T_SZ / 64, B_SZ * H_SZ);       // 16 x 24 = 384
    const dim3 gLOG(BT / 128, (V_SZ + 127) / 128); // 16 x 393

    for (int l = 0; l < L_SZ; l++) {
        const size_t wqOff = (size_t)l * E_SZ * QKV_LD;
        const size_t wOff  = (size_t)l * E_SZ * E_SZ;
        const size_t w1Off = (size_t)l * E_SZ * FF;
        const size_t vOff  = (size_t)l * E_SZ;
        const size_t fOff  = (size_t)l * FF;

        layernorm_kernel<<<BT, 256>>>(x, ln1_s + vOff, ln1_b + vOff, h);
        tgemm_k<128, false, 0><<<gQKV, 256, SM_G128F>>>(h, wqkv + wqOff, nullptr, nullptr,
                                                        qkv, QKV_LD, E_SZ);
        attn_kernel<<<gATT, 256, ATTN_SMEM>>>(qkv, att);
        tgemm_k<64, false, 5><<<gE, 256, SM_G64F>>>(att, wo + wOff, bo + vOff, x, x, E_SZ, E_SZ);
        layernorm_kernel<<<BT, 256>>>(x, ln2_s + vOff, ln2_b + vOff, h);
        tgemm_k<128, false, 11><<<gF, 256, SM_G128F>>>(h, w1 + w1Off, b1 + fOff, nullptr, m1, FF, E_SZ);
        tgemm_k<64, false, 5><<<gE, 256, SM_G64F>>>(m1, w2 + w1Off, b2 + vOff, x, x, E_SZ, FF);
    }

    layernorm_kernel<<<BT, 256>>>(x, lnf_s, lnf_b, h);
    tgemm_k<128, true, 0><<<gLOG, 256, SM_G128T>>>(h, wt, nullptr, nullptr, out, V_SZ, E_SZ);
}